// round 14
// baseline (speedup 1.0000x reference)
#include <cuda_runtime.h>
#include <cstdint>

// Problem constants
#define HID   1024
#define INP   128
#define NBAT  32
#define LSTEP 2048
#define KTOT  1152            // 1024 (h) + 128 (x)
#define COLS  64              // hidden columns per CTA (lane covers 2)
#define ROWSB 4               // batch rows per CTA
#define NCOLB 16              // column blocks (= CTAs per group)
#define NBATB 8               // batch groups
#define GRID  (NCOLB * NBATB) // 128 CTAs (single wave)
#define NTHR  512
#define NWARP 16
#define NCH   18              // 16 h-chunks + 2 x-chunks of 4k per warp
#define NWF   36              // f32x2 W regs (col0): 32 h + 4 x pairs

// Per-CTA epoch flags: one 64B sector per group (16 u32), line-padded.
// Single writer per slot; monotonic across launches/replays.
__device__ __align__(128) unsigned g_flags[NBATB][32];

__device__ __forceinline__ unsigned long long fma2(unsigned long long a,
                                                   unsigned long long b,
                                                   unsigned long long c) {
    unsigned long long d;
    asm("fma.rn.f32x2 %0, %1, %2, %3;" : "=l"(d) : "l"(a), "l"(b), "l"(c));
    return d;
}

__device__ __forceinline__ unsigned long long pack2(float x, float y) {
    unsigned long long r;
    asm("mov.b64 %0, {%1, %2};" : "=l"(r) : "f"(x), "f"(y));
    return r;
}

__device__ __forceinline__ float unpack_sum(unsigned long long v) {
    float lo, hi;
    asm("mov.b64 {%0, %1}, %2;" : "=f"(lo), "=f"(hi) : "l"(v));
    return lo + hi;
}

// K map: warp w owns h-k [64w, 64w+64) (chunks 0..15)
//        and x-k [1024+8w, 1024+8w+8) (chunks 16,17).
__device__ __forceinline__ int chunk_k(int w, int ch) {
    return (ch < 16) ? (64 * w + 4 * ch) : (HID + 8 * w + 4 * (ch - 16));
}

// smem layout (floats):
//   Ws   [288][32][4]     : 36864  (col1 W; [w*NCH+ch][lane][4k], k-map above)
//   HP   [ROWSB][KTOT]    :  4608  ([h | x] per row; h-segment [64w,64w+64)
//                                   is PRIVATE to warp w: only it writes/reads)
//   part [ROWSB][COLS][17]:  4352
//   bias [COLS]           :    64
#define SM_WS  0
#define SM_HP  (288 * 32 * 4)
#define SM_P   (SM_HP + ROWSB * KTOT)
#define PSTR   17
#define SM_B   (SM_P + ROWSB * COLS * PSTR)
#define SM_TOT (SM_B + COLS)            // 45888 floats = 183552 bytes

__global__ void __launch_bounds__(NTHR, 1)
reservoir_persistent(const float* __restrict__ input,   // (L, N, I)
                     const float* __restrict__ h_init,  // (N, H)
                     const float* __restrict__ W_in,    // (H, I)
                     const float* __restrict__ bias,    // (H)
                     const float* __restrict__ W_h,     // (H, H)
                     float* __restrict__ out)           // (L, N, H)
{
    extern __shared__ float smem[];
    float* Ws     = smem + SM_WS;
    float* HP     = smem + SM_HP;
    float* part_s = smem + SM_P;
    float* bias_s = smem + SM_B;

    const int tid = threadIdx.x;
    const int bx  = blockIdx.x;
    const int c   = bx & (NCOLB - 1);   // column block id (0..15)
    const int g   = bx >> 4;            // batch group id (0..7)
    const int j0  = c * COLS;
    const int n0  = g * ROWSB;

    // Epoch base: our OWN slot (single-writer -> race-free read).
    const unsigned base = *(volatile unsigned*)&g_flags[g][c];

    const int w    = tid >> 5;
    const int lane = tid & 31;
    const int col0 = j0 + lane;         // W in registers
    // col1 = j0 + 32 + lane            // W in shared

    // ---- One-time: W col0 into regs (k-map; all pair bases even) ----
    unsigned long long w0[NWF];
    #pragma unroll
    for (int i = 0; i < NWF; ++i) {
        int k = (i < 32) ? (64 * w + 2 * i) : (HID + 8 * w + 2 * (i - 32));
        float2 v;
        if (k < HID) v = *(const float2*)(W_h + (size_t)col0 * HID + k);
        else         v = *(const float2*)(W_in + (size_t)col0 * INP + (k - HID));
        w0[i] = pack2(v.x, v.y);
    }
    // ---- One-time: W col1 into shared (k-map) ----
    for (int i = tid; i < 288 * 32 * 4; i += NTHR) {
        int kk = i & 3;
        int l  = (i >> 2) & 31;
        int cg = i >> 7;
        int wp = cg / NCH, ch = cg % NCH;
        int k  = chunk_k(wp, ch) + kk;
        int cl = j0 + 32 + l;
        float v = (k < HID) ? W_h[(size_t)cl * HID + k]
                            : W_in[(size_t)cl * INP + (k - HID)];
        Ws[i] = v;
    }
    if (tid < COLS) bias_s[tid] = bias[j0 + tid];
    __syncthreads();

    const ulonglong2* wsp = (const ulonglong2*)Ws + (size_t)(w * NCH) * 32 + lane;
    const int rn = tid >> 6;            // reduce row (0..3), first 256 thr
    const int rj = tid & 63;            // reduce col (0..63)
    // h-slice staging indices: warp w stages 4 rows x 16 float4 of cols
    // [64w, 64w+64); lane covers i = lane, lane+32 -> row = i>>4, f4 = i&15.
    const int sr1 = lane >> 4,       sf1 = lane & 15;
    const int sr2 = (lane + 32) >> 4, sf2 = (lane + 32) & 15;

    volatile unsigned* myflag = &g_flags[g][w];

    for (int t = 0; t < LSTEP; ++t) {
        // ---- A: reduce step t-1 ∥ stage x(t); then release ----
        if (t > 0) {
            if (tid < 256) {
                float s = bias_s[rj];
                #pragma unroll
                for (int ww = 0; ww < NWARP; ++ww)
                    s += part_s[(rn * COLS + rj) * PSTR + ww];
                float hv = tanhf(s);
                out[((size_t)(t - 1) * NBAT + n0 + rn) * HID + j0 + rj] = hv;
            } else if (tid < 384) {
                // stage x(t) (HP x-region dead since previous compute; barI
                // of iter t-1 separates its readers from these writes)
                int n = (tid - 256) >> 5, q = tid & 31;
                float4 xv = ((const float4*)(input +
                             ((size_t)t * NBAT + n0 + n) * INP))[q];
                *(float4*)(HP + n * KTOT + HID + 4 * q) = xv;
            }
            __syncthreads();   // B: reduce STGs + x-stage complete
            if (tid == 0) {
                __threadfence();   // release: out[t-1] visible before flag
                *(volatile unsigned*)&g_flags[g][c] = base + (unsigned)t;
            }
        } else {
            if (tid < 128) {
                int n = tid >> 5, q = tid & 31;
                float4 xv = ((const float4*)(input + (size_t)(n0 + n) * INP))[q];
                *(float4*)(HP + n * KTOT + HID + 4 * q) = xv;
            }
            __syncthreads();
        }

        // ---- P: per-warp wait on our SINGLE producer (CTA w of our group) ----
        // All 32 lanes poll the same flag -> each thread verifies the full
        // condition (R2/R3-safe). Warp w==c skips: its h-slice is our own
        // reduce output, ordered intra-CTA by bar B.
        if (t > 0 && w != c) {
            const unsigned target = base + (unsigned)t;
            unsigned v = *myflag;
            while ((int)(v - target) < 0) v = *myflag;
            __threadfence();   // acquire
        }

        // ---- E: per-warp LDG of own h-slice (4 rows x cols [64w,64w+64)) ----
        const float* hsrc = (t == 0) ? (h_init + (size_t)n0 * HID)
                                     : (out + ((size_t)(t - 1) * NBAT + n0) * HID);
        float4 hA = *((const float4*)(hsrc + (size_t)sr1 * HID + 64 * w) + sf1);
        float4 hB = *((const float4*)(hsrc + (size_t)sr2 * HID + 64 * w) + sf2);

        unsigned long long acc[2 * ROWSB];
        #pragma unroll
        for (int i = 0; i < 2 * ROWSB; ++i) acc[i] = 0ull;

        // ---- x-chunks (16,17) first: absorb part of the h-LDG latency ----
        #pragma unroll
        for (int ch = 16; ch < 18; ++ch) {
            ulonglong2 wv = wsp[ch * 32];
            const char* xb = (const char*)HP + (size_t)(HID + 8 * w + 4 * (ch - 16)) * 4;
            #pragma unroll
            for (int r = 0; r < ROWSB; ++r) {
                ulonglong2 a = *(const ulonglong2*)(xb + r * (KTOT * 4));
                acc[2 * r]     = fma2(a.x, w0[32 + 2 * (ch - 16)],     acc[2 * r]);
                acc[2 * r]     = fma2(a.y, w0[32 + 2 * (ch - 16) + 1], acc[2 * r]);
                acc[2 * r + 1] = fma2(a.x, wv.x,                       acc[2 * r + 1]);
                acc[2 * r + 1] = fma2(a.y, wv.y,                       acc[2 * r + 1]);
            }
        }

        // ---- STS own h-slice into private HP segment; warp-local sync ----
        *((float4*)(HP + sr1 * KTOT + 64 * w) + sf1) = hA;
        *((float4*)(HP + sr2 * KTOT + 64 * w) + sf2) = hB;
        __syncwarp();

        // ---- G: h-chunks 0..15 (broadcast LDS from private segment) ----
        const char* hb = (const char*)HP + (size_t)(64 * w) * 4;
        #pragma unroll
        for (int ch = 0; ch < 16; ++ch) {
            ulonglong2 wv = wsp[ch * 32];
            #pragma unroll
            for (int r = 0; r < ROWSB; ++r) {
                ulonglong2 a = *(const ulonglong2*)(hb + r * (KTOT * 4) + 16 * ch);
                acc[2 * r]     = fma2(a.x, w0[2 * ch],     acc[2 * r]);
                acc[2 * r]     = fma2(a.y, w0[2 * ch + 1], acc[2 * r]);
                acc[2 * r + 1] = fma2(a.x, wv.x,           acc[2 * r + 1]);
                acc[2 * r + 1] = fma2(a.y, wv.y,           acc[2 * r + 1]);
            }
        }

        // ---- H: dump partials ----
        #pragma unroll
        for (int r = 0; r < ROWSB; ++r) {
            part_s[(r * COLS + lane) * PSTR + w]      = unpack_sum(acc[2 * r]);
            part_s[(r * COLS + 32 + lane) * PSTR + w] = unpack_sum(acc[2 * r + 1]);
        }
        __syncthreads();   // I: all partials in; next iter reduces them
    }

    // ---- Final: reduce step LSTEP-1 ----
    if (tid < 256) {
        float s = bias_s[rj];
        #pragma unroll
        for (int ww = 0; ww < NWARP; ++ww)
            s += part_s[(rn * COLS + rj) * PSTR + ww];
        float hv = tanhf(s);
        out[((size_t)(LSTEP - 1) * NBAT + n0 + rn) * HID + j0 + rj] = hv;
    }
}

extern "C" void kernel_launch(void* const* d_in, const int* in_sizes, int n_in,
                              void* d_out, int out_size) {
    (void)in_sizes; (void)n_in; (void)out_size;
    const float* input  = (const float*)d_in[0];  // (2048, 32, 128)
    const float* h_init = (const float*)d_in[1];  // (32, 1024)
    const float* W_in   = (const float*)d_in[2];  // (1024, 128)
    const float* bias   = (const float*)d_in[3];  // (1024)
    const float* W_h    = (const float*)d_in[4];  // (1024, 1024)
    float* out = (float*)d_out;                   // (2048, 32, 1024)

    cudaFuncSetAttribute(reservoir_persistent,
                         cudaFuncAttributeMaxDynamicSharedMemorySize,
                         SM_TOT * (int)sizeof(float));
    reservoir_persistent<<<GRID, NTHR, SM_TOT * sizeof(float)>>>(
        input, h_init, W_in, bias, W_h, out);
}

// round 15
// speedup vs baseline: 1.6448x; 1.6448x over previous
#include <cuda_runtime.h>
#include <cstdint>

// Problem constants
#define HID   1024
#define INP   128
#define NBAT  32
#define LSTEP 2048
#define KTOT  1152            // 1024 (h) + 128 (x)
#define COLS  64              // hidden columns per CTA (lane covers 2)
#define ROWSB 4               // batch rows per CTA
#define NCOLB 16              // column blocks (= CTAs per group)
#define NBATB 8               // batch groups
#define GRID  (NCOLB * NBATB) // 128 CTAs (single wave)
#define NCW   16              // compute warps
#define NTHR  544             // 16 compute warps + 1 poller warp
#define NCH   18              // 16 h-chunks + 2 x-chunks of 4k per warp
#define NWF   36              // f32x2 W regs (col0): 32 h + 4 x pairs

// Per-CTA epoch flags: one 64B sector per group (16 u32), line-padded.
// Single writer per slot; monotonic across launches/replays.
__device__ __align__(128) unsigned g_flags[NBATB][32];

__device__ __forceinline__ unsigned long long fma2(unsigned long long a,
                                                   unsigned long long b,
                                                   unsigned long long c) {
    unsigned long long d;
    asm("fma.rn.f32x2 %0, %1, %2, %3;" : "=l"(d) : "l"(a), "l"(b), "l"(c));
    return d;
}

__device__ __forceinline__ unsigned long long pack2(float x, float y) {
    unsigned long long r;
    asm("mov.b64 %0, {%1, %2};" : "=l"(r) : "f"(x), "f"(y));
    return r;
}

__device__ __forceinline__ float unpack_sum(unsigned long long v) {
    float lo, hi;
    asm("mov.b64 {%0, %1}, %2;" : "=f"(lo), "=f"(hi) : "l"(v));
    return lo + hi;
}

// K map: warp w owns h-k [64w, 64w+64) (chunks 0..15) -> producer CTA w,
//        and x-k [1024+8w, 1024+8w+8) (chunks 16,17).
__device__ __forceinline__ int chunk_k(int w, int ch) {
    return (ch < 16) ? (64 * w + 4 * ch) : (HID + 8 * w + 4 * (ch - 16));
}

// smem layout (floats):
//   Ws   [288][32][4]     : 36864  (col1 W; [w*NCH+ch][lane][4k], k-map)
//   HP   [ROWSB][KTOT]    :  4608  (h-seg [64w,64w+64) PRIVATE to warp w)
//   part [ROWSB][COLS][17]:  4352
//   bias [COLS]           :    64
//   tok  [16]             :    16  (per-producer ready tokens, launch-local)
#define SM_WS  0
#define SM_HP  (288 * 32 * 4)
#define SM_P   (SM_HP + ROWSB * KTOT)
#define PSTR   17
#define SM_B   (SM_P + ROWSB * COLS * PSTR)
#define SM_TOK (SM_B + COLS)
#define SM_TOT (SM_TOK + 16)            // 45904 floats = 183616 bytes

__global__ void __launch_bounds__(NTHR, 1)
reservoir_persistent(const float* __restrict__ input,   // (L, N, I)
                     const float* __restrict__ h_init,  // (N, H)
                     const float* __restrict__ W_in,    // (H, I)
                     const float* __restrict__ bias,    // (H)
                     const float* __restrict__ W_h,     // (H, H)
                     float* __restrict__ out)           // (L, N, H)
{
    extern __shared__ float smem[];
    float* Ws     = smem + SM_WS;
    float* HP     = smem + SM_HP;
    float* part_s = smem + SM_P;
    float* bias_s = smem + SM_B;
    volatile unsigned* tok_s = (volatile unsigned*)(smem + SM_TOK);

    const int tid = threadIdx.x;
    const int bx  = blockIdx.x;
    const int c   = bx & (NCOLB - 1);   // column block id (0..15)
    const int g   = bx >> 4;            // batch group id (0..7)
    const int j0  = c * COLS;
    const int n0  = g * ROWSB;

    // Epoch base: our OWN slot (single-writer -> race-free read).
    const unsigned base = *(volatile unsigned*)&g_flags[g][c];

    const int w    = tid >> 5;          // 0..15 compute, 16 poller
    const int lane = tid & 31;
    const int col0 = j0 + lane;         // W in registers
    // col1 = j0 + 32 + lane            // W in shared

    // ---- One-time: W col0 into regs (compute warps only; k-map) ----
    unsigned long long w0[NWF];
    if (w < NCW) {
        #pragma unroll
        for (int i = 0; i < NWF; ++i) {
            int k = (i < 32) ? (64 * w + 2 * i) : (HID + 8 * w + 2 * (i - 32));
            float2 v;
            if (k < HID) v = *(const float2*)(W_h + (size_t)col0 * HID + k);
            else         v = *(const float2*)(W_in + (size_t)col0 * INP + (k - HID));
            w0[i] = pack2(v.x, v.y);
        }
    }
    // ---- One-time: W col1 into shared (k-map) ----
    for (int i = tid; i < 288 * 32 * 4; i += NTHR) {
        int kk = i & 3;
        int l  = (i >> 2) & 31;
        int cg = i >> 7;
        int wp = cg / NCH, ch = cg % NCH;
        int k  = chunk_k(wp, ch) + kk;
        int cl = j0 + 32 + l;
        float v = (k < HID) ? W_h[(size_t)cl * HID + k]
                            : W_in[(size_t)cl * INP + (k - HID)];
        Ws[i] = v;
    }
    if (tid < COLS) bias_s[tid] = bias[j0 + tid];
    if (tid < 16)   tok_s[tid]  = 0u;   // launch-local tokens
    // Prologue: stage x(0)
    if (tid < 128) {
        int n = tid >> 5, q = tid & 31;
        float4 xv = ((const float4*)(input + (size_t)(n0 + n) * INP))[q];
        *(float4*)(HP + n * KTOT + HID + 4 * q) = xv;
    }
    __syncthreads();

    const ulonglong2* wsp = (const ulonglong2*)Ws + (size_t)(w * NCH) * 32 + lane;
    const int rn = tid >> 6;            // reduce row (0..3), first 256 thr
    const int rj = tid & 63;            // reduce col (0..63)
    const int sr1 = lane >> 4,        sf1 = lane & 15;   // h-slice stage idx
    const int sr2 = (lane + 32) >> 4, sf2 = (lane + 32) & 15;

    for (int t = 0; t < LSTEP; ++t) {
        if (t > 0) {
            if (w == NCW) {
                // ---- Poller warp: poll 16 flags (one 64B sector, one L2
                // RT per retry), release smem token per producer as it
                // lands. Single L2 poller per CTA (R14's storm fixed).
                if (lane < 16) {
                    const unsigned target = base + (unsigned)t;
                    volatile unsigned* fp = &g_flags[g][lane];
                    bool done = false;
                    do {
                        if (!done) {
                            unsigned v = *fp;
                            if ((int)(v - target) >= 0) {
                                __threadfence();       // acquire producer's out
                                tok_s[lane] = (unsigned)t;   // release token
                                done = true;
                            }
                        }
                    } while (!__all_sync(0x0000FFFFu, done));
                }
            } else {
                // ---- A: reduce t-1 (warps 0-7) ∥ stage x(t) (warps 8-11) ----
                if (tid < 256) {
                    float s = bias_s[rj];
                    #pragma unroll
                    for (int ww = 0; ww < NCW; ++ww)
                        s += part_s[(rn * COLS + rj) * PSTR + ww];
                    float hv = tanhf(s);
                    out[((size_t)(t - 1) * NBAT + n0 + rn) * HID + j0 + rj] = hv;
                } else if (tid < 384) {
                    int n = (tid - 256) >> 5, q = tid & 31;
                    float4 xv = ((const float4*)(input +
                                 ((size_t)t * NBAT + n0 + n) * INP))[q];
                    *(float4*)(HP + n * KTOT + HID + 4 * q) = xv;
                }
                // B: named barrier over compute warps (512 thr): orders
                // reduce STGs + x-stage before release and before compute.
                asm volatile("bar.sync 1, 512;" ::: "memory");
                if (tid == 0) {
                    __threadfence();   // release: out[t-1] before flag
                    *(volatile unsigned*)&g_flags[g][c] = base + (unsigned)t;
                }
                // ---- Per-warp token wait (smem spin; no L2 traffic).
                // Own producer (w==c): data ordered intra-CTA by bar B.
                if (w != c) {
                    while ((int)(tok_s[w] - (unsigned)t) < 0) { }
                    __threadfence_block();
                }
            }
        }

        // ---- Compute section (warps 0..15) ----
        if (w < NCW) {
            const float* hsrc = (t == 0)
                ? (h_init + (size_t)n0 * HID)
                : (out + ((size_t)(t - 1) * NBAT + n0) * HID);
            // E: per-warp LDG of own h-slice (4 rows x cols [64w,64w+64))
            float4 hA = *((const float4*)(hsrc + (size_t)sr1 * HID + 64 * w) + sf1);
            float4 hB = *((const float4*)(hsrc + (size_t)sr2 * HID + 64 * w) + sf2);

            unsigned long long acc[2 * ROWSB];
            #pragma unroll
            for (int i = 0; i < 2 * ROWSB; ++i) acc[i] = 0ull;

            // x-chunks first: absorb h-LDG latency
            #pragma unroll
            for (int ch = 16; ch < 18; ++ch) {
                ulonglong2 wv = wsp[ch * 32];
                const char* xb = (const char*)HP +
                                 (size_t)(HID + 8 * w + 4 * (ch - 16)) * 4;
                #pragma unroll
                for (int r = 0; r < ROWSB; ++r) {
                    ulonglong2 a = *(const ulonglong2*)(xb + r * (KTOT * 4));
                    acc[2 * r]     = fma2(a.x, w0[32 + 2 * (ch - 16)],     acc[2 * r]);
                    acc[2 * r]     = fma2(a.y, w0[32 + 2 * (ch - 16) + 1], acc[2 * r]);
                    acc[2 * r + 1] = fma2(a.x, wv.x,                       acc[2 * r + 1]);
                    acc[2 * r + 1] = fma2(a.y, wv.y,                       acc[2 * r + 1]);
                }
            }

            // STS own h-slice into private HP segment; warp-local sync
            *((float4*)(HP + sr1 * KTOT + 64 * w) + sf1) = hA;
            *((float4*)(HP + sr2 * KTOT + 64 * w) + sf2) = hB;
            __syncwarp();

            // G: h-chunks 0..15 (broadcast LDS from private segment)
            const char* hb = (const char*)HP + (size_t)(64 * w) * 4;
            #pragma unroll
            for (int ch = 0; ch < 16; ++ch) {
                ulonglong2 wv = wsp[ch * 32];
                #pragma unroll
                for (int r = 0; r < ROWSB; ++r) {
                    ulonglong2 a = *(const ulonglong2*)(hb + r * (KTOT * 4) + 16 * ch);
                    acc[2 * r]     = fma2(a.x, w0[2 * ch],     acc[2 * r]);
                    acc[2 * r]     = fma2(a.y, w0[2 * ch + 1], acc[2 * r]);
                    acc[2 * r + 1] = fma2(a.x, wv.x,           acc[2 * r + 1]);
                    acc[2 * r + 1] = fma2(a.y, wv.y,           acc[2 * r + 1]);
                }
            }

            // H: dump partials
            #pragma unroll
            for (int r = 0; r < ROWSB; ++r) {
                part_s[(r * COLS + lane) * PSTR + w]      = unpack_sum(acc[2 * r]);
                part_s[(r * COLS + 32 + lane) * PSTR + w] = unpack_sum(acc[2 * r + 1]);
            }
        }
        __syncthreads();   // I: partials in; poller joined; next iter safe
    }

    // ---- Final: reduce step LSTEP-1 ----
    if (tid < 256) {
        float s = bias_s[rj];
        #pragma unroll
        for (int ww = 0; ww < NCW; ++ww)
            s += part_s[(rn * COLS + rj) * PSTR + ww];
        float hv = tanhf(s);
        out[((size_t)(LSTEP - 1) * NBAT + n0 + rn) * HID + j0 + rj] = hv;
    }
}

extern "C" void kernel_launch(void* const* d_in, const int* in_sizes, int n_in,
                              void* d_out, int out_size) {
    (void)in_sizes; (void)n_in; (void)out_size;
    const float* input  = (const float*)d_in[0];  // (2048, 32, 128)
    const float* h_init = (const float*)d_in[1];  // (32, 1024)
    const float* W_in   = (const float*)d_in[2];  // (1024, 128)
    const float* bias   = (const float*)d_in[3];  // (1024)
    const float* W_h    = (const float*)d_in[4];  // (1024, 1024)
    float* out = (float*)d_out;                   // (2048, 32, 1024)

    cudaFuncSetAttribute(reservoir_persistent,
                         cudaFuncAttributeMaxDynamicSharedMemorySize,
                         SM_TOT * (int)sizeof(float));
    reservoir_persistent<<<GRID, NTHR, SM_TOT * sizeof(float)>>>(
        input, h_init, W_in, bias, W_h, out);
}

// round 16
// speedup vs baseline: 2.2882x; 1.3912x over previous
#include <cuda_runtime.h>
#include <cstdint>

// Problem constants
#define HID   1024
#define INP   128
#define NBAT  32
#define LSTEP 2048
#define KTOT  1152            // 1024 (h) + 128 (x)
#define COLS  64              // hidden columns per CTA (lane covers 2)
#define ROWSB 4               // batch rows per CTA
#define NCOLB 16              // column blocks (= CTAs per group)
#define NBATB 8               // batch groups
#define GRID  (NCOLB * NBATB) // 128 CTAs (single wave)
#define NCW   16              // compute warps (warp 15 dual-duty: poller)
#define NTHR  512             // 128-reg budget preserved
#define NCH   18              // 16 h-chunks + 2 x-chunks of 4k per warp
#define NWF   36              // f32x2 W regs (col0): 32 h + 4 x pairs

// Per-CTA epoch flags: one 64B sector per group (16 u32), line-padded.
// Single writer per slot; monotonic across launches/replays.
__device__ __align__(128) unsigned g_flags[NBATB][32];

__device__ __forceinline__ unsigned long long fma2(unsigned long long a,
                                                   unsigned long long b,
                                                   unsigned long long c) {
    unsigned long long d;
    asm("fma.rn.f32x2 %0, %1, %2, %3;" : "=l"(d) : "l"(a), "l"(b), "l"(c));
    return d;
}

__device__ __forceinline__ unsigned long long pack2(float x, float y) {
    unsigned long long r;
    asm("mov.b64 %0, {%1, %2};" : "=l"(r) : "f"(x), "f"(y));
    return r;
}

__device__ __forceinline__ float unpack_sum(unsigned long long v) {
    float lo, hi;
    asm("mov.b64 {%0, %1}, %2;" : "=f"(lo), "=f"(hi) : "l"(v));
    return lo + hi;
}

// K map: warp w owns h-k [64w, 64w+64) (chunks 0..15) -> producer CTA w,
//        and x-k [1024+8w, 1024+8w+8) (chunks 16,17).
__device__ __forceinline__ int chunk_k(int w, int ch) {
    return (ch < 16) ? (64 * w + 4 * ch) : (HID + 8 * w + 4 * (ch - 16));
}

// smem layout (floats):
//   Ws   [288][32][4]     : 36864  (col1 W; [w*NCH+ch][lane][4k], k-map)
//   HP   [ROWSB][KTOT]    :  4608  (h-seg [64w,64w+64) PRIVATE to warp w)
//   part [ROWSB][COLS][17]:  4352
//   bias [COLS]           :    64
//   tok  [16]             :    16  (per-producer ready tokens, launch-local)
#define SM_WS  0
#define SM_HP  (288 * 32 * 4)
#define SM_P   (SM_HP + ROWSB * KTOT)
#define PSTR   17
#define SM_B   (SM_P + ROWSB * COLS * PSTR)
#define SM_TOK (SM_B + COLS)
#define SM_TOT (SM_TOK + 16)            // 45904 floats = 183616 bytes

__global__ void __launch_bounds__(NTHR, 1)
reservoir_persistent(const float* __restrict__ input,   // (L, N, I)
                     const float* __restrict__ h_init,  // (N, H)
                     const float* __restrict__ W_in,    // (H, I)
                     const float* __restrict__ bias,    // (H)
                     const float* __restrict__ W_h,     // (H, H)
                     float* __restrict__ out)           // (L, N, H)
{
    extern __shared__ float smem[];
    float* Ws     = smem + SM_WS;
    float* HP     = smem + SM_HP;
    float* part_s = smem + SM_P;
    float* bias_s = smem + SM_B;
    volatile unsigned* tok_s = (volatile unsigned*)(smem + SM_TOK);

    const int tid = threadIdx.x;
    const int bx  = blockIdx.x;
    const int c   = bx & (NCOLB - 1);   // column block id (0..15)
    const int g   = bx >> 4;            // batch group id (0..7)
    const int j0  = c * COLS;
    const int n0  = g * ROWSB;

    // Epoch base: our OWN slot (single-writer -> race-free read).
    const unsigned base = *(volatile unsigned*)&g_flags[g][c];

    const int w    = tid >> 5;          // 0..15 (warp 15 also polls)
    const int lane = tid & 31;
    const int col0 = j0 + lane;         // W in registers
    // col1 = j0 + 32 + lane            // W in shared

    // ---- One-time: W col0 into regs (k-map; all pair bases even) ----
    unsigned long long w0[NWF];
    #pragma unroll
    for (int i = 0; i < NWF; ++i) {
        int k = (i < 32) ? (64 * w + 2 * i) : (HID + 8 * w + 2 * (i - 32));
        float2 v;
        if (k < HID) v = *(const float2*)(W_h + (size_t)col0 * HID + k);
        else         v = *(const float2*)(W_in + (size_t)col0 * INP + (k - HID));
        w0[i] = pack2(v.x, v.y);
    }
    // ---- One-time: W col1 into shared (k-map) ----
    for (int i = tid; i < 288 * 32 * 4; i += NTHR) {
        int kk = i & 3;
        int l  = (i >> 2) & 31;
        int cg = i >> 7;
        int wp = cg / NCH, ch = cg % NCH;
        int k  = chunk_k(wp, ch) + kk;
        int cl = j0 + 32 + l;
        float v = (k < HID) ? W_h[(size_t)cl * HID + k]
                            : W_in[(size_t)cl * INP + (k - HID)];
        Ws[i] = v;
    }
    if (tid < COLS) bias_s[tid] = bias[j0 + tid];
    if (tid < 16)   tok_s[tid]  = 0u;   // launch-local tokens
    // Prologue: stage x(0)
    if (tid < 128) {
        int n = tid >> 5, q = tid & 31;
        float4 xv = ((const float4*)(input + (size_t)(n0 + n) * INP))[q];
        *(float4*)(HP + n * KTOT + HID + 4 * q) = xv;
    }
    __syncthreads();

    const ulonglong2* wsp = (const ulonglong2*)Ws + (size_t)(w * NCH) * 32 + lane;
    const int rn = tid >> 6;            // reduce row (0..3), first 256 thr
    const int rj = tid & 63;            // reduce col (0..63)
    const int sr1 = lane >> 4,        sf1 = lane & 15;   // h-slice stage idx
    const int sr2 = (lane + 32) >> 4, sf2 = (lane + 32) & 15;

    for (int t = 0; t < LSTEP; ++t) {
        if (t > 0) {
            // ---- A: reduce t-1 (warps 0-7) ∥ stage x(t) (warps 8-11) ----
            if (tid < 256) {
                float s = bias_s[rj];
                #pragma unroll
                for (int ww = 0; ww < NCW; ++ww)
                    s += part_s[(rn * COLS + rj) * PSTR + ww];
                float hv = tanhf(s);
                out[((size_t)(t - 1) * NBAT + n0 + rn) * HID + j0 + rj] = hv;
            } else if (tid < 384) {
                int n = (tid - 256) >> 5, q = tid & 31;
                float4 xv = ((const float4*)(input +
                             ((size_t)t * NBAT + n0 + n) * INP))[q];
                *(float4*)(HP + n * KTOT + HID + 4 * q) = xv;
            }
            __syncthreads();   // B: reduce STGs + x-stage done; part_s free
            if (tid == 0) {
                __threadfence();   // release: out[t-1] visible before flag
                *(volatile unsigned*)&g_flags[g][c] = base + (unsigned)t;
            }

            if (w == NCW - 1) {
                // ---- Poller (warp 15, post-release as in R11): poll 16
                // flags in one 64B sector; release a smem token per
                // producer AS IT LANDS. Then compute (no token needed:
                // the poll acquired every producer, incl. our own CTA).
                if (lane < 16) {
                    const unsigned target = base + (unsigned)t;
                    volatile unsigned* fp = &g_flags[g][lane];
                    bool done = false;
                    do {
                        if (!done) {
                            unsigned v = *fp;
                            if ((int)(v - target) >= 0) {
                                __threadfence();           // acquire
                                tok_s[lane] = (unsigned)t; // token release
                                done = true;
                            }
                        }
                    } while (!__all_sync(0x0000FFFFu, done));
                }
                __syncwarp();
            } else if (w != c) {
                // ---- Per-warp token wait: smem spin, zero L2 traffic.
                // All 32 lanes verify the same full condition (R2/3-safe).
                while ((int)(tok_s[w] - (unsigned)t) < 0) { }
                __threadfence();   // acquire producer's global writes
            }
            // w == c (w != 15): own reduce output; ordered by bar B.
        }

        // ---- E: per-warp LDG of own h-slice (4 rows x cols [64w,64w+64)) ----
        const float* hsrc = (t == 0)
            ? (h_init + (size_t)n0 * HID)
            : (out + ((size_t)(t - 1) * NBAT + n0) * HID);
        float4 hA = *((const float4*)(hsrc + (size_t)sr1 * HID + 64 * w) + sf1);
        float4 hB = *((const float4*)(hsrc + (size_t)sr2 * HID + 64 * w) + sf2);

        unsigned long long acc[2 * ROWSB];
        #pragma unroll
        for (int i = 0; i < 2 * ROWSB; ++i) acc[i] = 0ull;

        // ---- x-chunks (16,17) first: absorb h-LDG latency ----
        #pragma unroll
        for (int ch = 16; ch < 18; ++ch) {
            ulonglong2 wv = wsp[ch * 32];
            const char* xb = (const char*)HP +
                             (size_t)(HID + 8 * w + 4 * (ch - 16)) * 4;
            #pragma unroll
            for (int r = 0; r < ROWSB; ++r) {
                ulonglong2 a = *(const ulonglong2*)(xb + r * (KTOT * 4));
                acc[2 * r]     = fma2(a.x, w0[32 + 2 * (ch - 16)],     acc[2 * r]);
                acc[2 * r]     = fma2(a.y, w0[32 + 2 * (ch - 16) + 1], acc[2 * r]);
                acc[2 * r + 1] = fma2(a.x, wv.x,                       acc[2 * r + 1]);
                acc[2 * r + 1] = fma2(a.y, wv.y,                       acc[2 * r + 1]);
            }
        }

        // ---- STS own h-slice into private HP segment; warp-local sync ----
        *((float4*)(HP + sr1 * KTOT + 64 * w) + sf1) = hA;
        *((float4*)(HP + sr2 * KTOT + 64 * w) + sf2) = hB;
        __syncwarp();

        // ---- G: h-chunks 0..15 (broadcast LDS from private segment) ----
        const char* hb = (const char*)HP + (size_t)(64 * w) * 4;
        #pragma unroll
        for (int ch = 0; ch < 16; ++ch) {
            ulonglong2 wv = wsp[ch * 32];
            #pragma unroll
            for (int r = 0; r < ROWSB; ++r) {
                ulonglong2 a = *(const ulonglong2*)(hb + r * (KTOT * 4) + 16 * ch);
                acc[2 * r]     = fma2(a.x, w0[2 * ch],     acc[2 * r]);
                acc[2 * r]     = fma2(a.y, w0[2 * ch + 1], acc[2 * r]);
                acc[2 * r + 1] = fma2(a.x, wv.x,           acc[2 * r + 1]);
                acc[2 * r + 1] = fma2(a.y, wv.y,           acc[2 * r + 1]);
            }
        }

        // ---- H: dump partials ----
        #pragma unroll
        for (int r = 0; r < ROWSB; ++r) {
            part_s[(r * COLS + lane) * PSTR + w]      = unpack_sum(acc[2 * r]);
            part_s[(r * COLS + 32 + lane) * PSTR + w] = unpack_sum(acc[2 * r + 1]);
        }
        __syncthreads();   // I: all partials in; next iter's reduce reads them
    }

    // ---- Final: reduce step LSTEP-1 ----
    if (tid < 256) {
        float s = bias_s[rj];
        #pragma unroll
        for (int ww = 0; ww < NCW; ++ww)
            s += part_s[(rn * COLS + rj) * PSTR + ww];
        float hv = tanhf(s);
        out[((size_t)(LSTEP - 1) * NBAT + n0 + rn) * HID + j0 + rj] = hv;
    }
}

extern "C" void kernel_launch(void* const* d_in, const int* in_sizes, int n_in,
                              void* d_out, int out_size) {
    (void)in_sizes; (void)n_in; (void)out_size;
    const float* input  = (const float*)d_in[0];  // (2048, 32, 128)
    const float* h_init = (const float*)d_in[1];  // (32, 1024)
    const float* W_in   = (const float*)d_in[2];  // (1024, 128)
    const float* bias   = (const float*)d_in[3];  // (1024)
    const float* W_h    = (const float*)d_in[4];  // (1024, 1024)
    float* out = (float*)d_out;                   // (2048, 32, 1024)

    cudaFuncSetAttribute(reservoir_persistent,
                         cudaFuncAttributeMaxDynamicSharedMemorySize,
                         SM_TOT * (int)sizeof(float));
    reservoir_persistent<<<GRID, NTHR, SM_TOT * sizeof(float)>>>(
        input, h_init, W_in, bias, W_h, out);
}